// round 15
// baseline (speedup 1.0000x reference)
#include <cuda_runtime.h>
#include <cuda_fp16.h>
#include <cstdint>

// ---------------- problem dims ----------------
#define CIN   32
#define COUT  32
#define HIN   512
#define WIN   512
#define HOUT  510
#define WOUT  510
#define NB    16

// ---------------- tiling ----------------
#define TY      4              // output rows per tile (1 per warp)
#define TPX     64             // output px per CTA (n64 per warp)
#define XPX     68             // staged px (64 + 2 halo + pad)
#define THREADS 128            // 4 fat warps
#define NTILES  8              // y-tiles walked per CTA

// ---------------- smem ----------------
#define ROWB       80
#define XSLOT      (XPX * ROWB)         // 5440
#define RSLOTS     10
#define RING_BYTES (RSLOTS * XSLOT)     // 54400
#define FROW       272
#define FSLOT      (32 * FROW)          // 8704
#define F_OFF      RING_BYTES           // 54400
#define F_BYTES    (4 * FSLOT)          // 34816
#define W_OFF      (F_OFF + F_BYTES)    // 89216
#define W_BYTES    (288 * ROWB)         // 23040
#define SMEM_TOTAL (W_OFF + W_BYTES)    // 112256 (2 CTAs/SM)

__device__ __align__(16) __half w_packed[288 * 40];

__device__ __forceinline__ uint32_t smem_u32(const void* p) {
    uint32_t a;
    asm("{ .reg .u64 t; cvta.to.shared.u64 t, %1; cvt.u32.u64 %0, t; }"
        : "=r"(a) : "l"(p));
    return a;
}
__device__ __forceinline__ uint32_t h2u(__half2 h) {
    return *reinterpret_cast<uint32_t*>(&h);
}

#define STS128(addr, a, b, c, d) \
    asm volatile("st.shared.v4.b32 [%0], {%1,%2,%3,%4};" \
        :: "r"(addr), "r"(a), "r"(b), "r"(c), "r"(d) : "memory")

#define LDSM4(r, addr) \
    asm volatile("ldmatrix.sync.aligned.m8n8.x4.shared.b16 {%0,%1,%2,%3}, [%4];" \
        : "=r"((r)[0]), "=r"((r)[1]), "=r"((r)[2]), "=r"((r)[3]) : "r"(addr))

#define MMA_F16(c, a, b0, b1) \
    asm volatile("mma.sync.aligned.m16n8k16.row.col.f32.f16.f16.f32 " \
        "{%0,%1,%2,%3}, {%4,%5,%6,%7}, {%8,%9}, {%0,%1,%2,%3};" \
        : "+f"((c)[0]), "+f"((c)[1]), "+f"((c)[2]), "+f"((c)[3]) \
        : "r"((a)[0]), "r"((a)[1]), "r"((a)[2]), "r"((a)[3]), "r"(b0), "r"(b1))

#define CP_ASYNC16(smem, gmem) \
    asm volatile("cp.async.cg.shared.global [%0], [%1], 16;" \
        :: "r"(smem), "l"(gmem) : "memory")
#define CP_COMMIT()  asm volatile("cp.async.commit_group;" ::: "memory")
#define CP_WAIT0()   asm volatile("cp.async.wait_group 0;" ::: "memory")

// =====================================================================
// setup: w (OIHW fp32) -> w_packed [kk*32+co][ci] fp16 (40-half rows)
// =====================================================================
__global__ void pack_w_kernel(const float* __restrict__ w)
{
    int i = blockIdx.x * 256 + threadIdx.x;
    if (i < 288 * 32) {
        int row = i >> 5;
        int ci  = i & 31;
        int kk  = row >> 5;
        int co  = row & 31;
        w_packed[row * 40 + ci] = __float2half_rn(w[(co * 32 + ci) * 9 + kk]);
    }
}

// =====================================================================
// staging helpers
// =====================================================================
__device__ __forceinline__ void issue_rows(const float* __restrict__ x,
                                           uint32_t sb, int nb, int x0,
                                           int base_row, int nrows, int t)
{
    const int nchunks = nrows * 32 * 17;
    #pragma unroll 1
    for (int chunk = t; chunk < nchunks; chunk += THREADS) {
        const int k   = chunk % 17;
        const int rem = chunk / 17;
        const int ci  = rem & 31;
        const int j   = rem >> 5;
        const int y_in = base_row + j;
        const int gx0  = x0 + k * 4;
        if (y_in < HIN && gx0 + 3 < WIN) {
            const float* g =
                x + ((size_t)(nb * CIN + ci) * HIN + y_in) * WIN + gx0;
            CP_ASYNC16(sb + F_OFF + (uint32_t)((j * 32 + ci) * FROW + k * 16), g);
        }
    }
}

__device__ __forceinline__ void convert_rows(const char* smem, uint32_t sb,
                                             int base_row, int nrows, int t)
{
    const float* fs = reinterpret_cast<const float*>(smem + F_OFF);
    const int items = nrows * 4 * XPX;
    #pragma unroll 1
    for (int it = t; it < items; it += THREADS) {
        const int px  = it % XPX;
        const int rem = it / XPX;
        const int o   = rem & 3;
        const int j   = rem >> 2;
        const int slot = (base_row + j) % RSLOTS;
        const float* src = fs + (j * 32 + o * 8) * XPX + px;
        float v[8];
        #pragma unroll
        for (int q = 0; q < 8; ++q) v[q] = src[q * XPX];
        __half2 h0 = __floats2half2_rn(v[0], v[1]);
        __half2 h1 = __floats2half2_rn(v[2], v[3]);
        __half2 h2 = __floats2half2_rn(v[4], v[5]);
        __half2 h3 = __floats2half2_rn(v[6], v[7]);
        STS128(sb + (uint32_t)slot * XSLOT + (uint32_t)px * ROWB + (uint32_t)o * 16,
               h2u(h0), h2u(h1), h2u(h2), h2u(h3));
    }
}

// =====================================================================
// main kernel: 4 fat warps, m32 x n64 per warp, ring-buffered persistent
// =====================================================================
__global__ __launch_bounds__(THREADS, 2)
void conv_mma_kernel(const float* __restrict__ x,
                     const float* __restrict__ bias,
                     float* __restrict__ out)
{
    extern __shared__ char smem[];
    const uint32_t sb = smem_u32(smem);
    const int t    = threadIdx.x;
    const int wid  = t >> 5;        // 0..3 = output row
    const int lane = t & 31;

    const int xt  = blockIdx.x;           // 0..7
    const int gy  = blockIdx.y;           // 0..15
    const int nb  = blockIdx.z;           // 0..15
    const int x0  = xt * TPX;
    const int yt0 = gy * NTILES;
    const int row0 = yt0 * TY;

    // ---- stage W once per CTA
    {
        const uint4* src = reinterpret_cast<const uint4*>(w_packed);
        #pragma unroll 1
        for (int i = t; i < W_BYTES / 16; i += THREADS) {
            uint4 v = src[i];
            STS128(sb + W_OFF + (uint32_t)i * 16, v.x, v.y, v.z, v.w);
        }
    }

    // ---- prologue: rows row0..row0+3, then row0+4..row0+5
    issue_rows(x, sb, nb, x0, row0, 4, t);
    CP_COMMIT(); CP_WAIT0(); __syncthreads();
    convert_rows(smem, sb, row0, 4, t);
    __syncthreads();
    issue_rows(x, sb, nb, x0, row0 + 4, 2, t);
    CP_COMMIT(); CP_WAIT0(); __syncthreads();
    convert_rows(smem, sb, row0 + 4, 2, t);
    __syncthreads();

    // lane constants
    const int a_row   = lane & 15;
    const int a_chunk = lane >> 4;
    const int b_n     = (lane & 7) | ((lane >> 4) << 3);
    const int b_chunk = (lane >> 3) & 1;
    const int g  = lane >> 2;
    const int tg = lane & 3;

    const int r = wid;                 // output row within tile

    float bv[2][2];
    #pragma unroll
    for (int mt = 0; mt < 2; ++mt) {
        bv[mt][0] = __ldg(bias + mt * 16 + g);
        bv[mt][1] = __ldg(bias + mt * 16 + 8 + g);
    }

    #pragma unroll 1
    for (int i = 0; i < NTILES; ++i) {
        const int yin0 = (yt0 + i) * TY;

        // ---- prefetch the 4 new rows for tile i+1
        if (i + 1 < NTILES) {
            issue_rows(x, sb, nb, x0, yin0 + 6, 4, t);
            CP_COMMIT();
        }

        // ---- compute tile i: m32 co x n64 px per warp
        float c[2][8][4];
        #pragma unroll
        for (int mt = 0; mt < 2; ++mt)
            #pragma unroll
            for (int q = 0; q < 8; ++q) {
                c[mt][q][0] = bv[mt][0]; c[mt][q][1] = bv[mt][0];
                c[mt][q][2] = bv[mt][1]; c[mt][q][3] = bv[mt][1];
            }

        #pragma unroll
        for (int ky = 0; ky < 3; ++ky) {
            const int srow = yin0 + r + ky;
            const uint32_t Xs = sb + (uint32_t)(srow % RSLOTS) * XSLOT;
            #pragma unroll
            for (int kx = 0; kx < 3; ++kx) {
                const int kk = ky * 3 + kx;
                const uint32_t aBase =
                    sb + W_OFF + (uint32_t)(kk * 32 + a_row) * ROWB;
                #pragma unroll
                for (int kc = 0; kc < 2; ++kc) {
                    const uint32_t aOff = (uint32_t)(2 * kc + a_chunk) * 16;
                    const uint32_t bOff = (uint32_t)(2 * kc + b_chunk) * 16;

                    uint32_t a[2][4];
                    LDSM4(a[0], aBase + aOff);
                    LDSM4(a[1], aBase + 16 * ROWB + aOff);

                    uint32_t b[4][4];
                    #pragma unroll
                    for (int g2 = 0; g2 < 4; ++g2) {   // four n16 groups
                        const int prow = kx + g2 * 16 + b_n;
                        LDSM4(b[g2], Xs + (uint32_t)prow * ROWB + bOff);
                    }
                    #pragma unroll
                    for (int mt = 0; mt < 2; ++mt)
                        #pragma unroll
                        for (int q = 0; q < 8; ++q) {
                            const int g2 = q >> 1;
                            const int e  = (q & 1) * 2;
                            MMA_F16(c[mt][q], a[mt], b[g2][e], b[g2][e + 1]);
                        }
                }
            }
        }

        // ---- store
        const int oy = yin0 + r;
        if (oy < HOUT) {
            #pragma unroll
            for (int mt = 0; mt < 2; ++mt) {
                const size_t base0 =
                    ((size_t)(nb * COUT + mt * 16 + g) * HOUT + oy) * (size_t)WOUT;
                const size_t coStep = (size_t)8 * HOUT * WOUT;
                #pragma unroll
                for (int q = 0; q < 8; ++q) {
                    const int ox = x0 + q * 8 + 2 * tg;
                    if (ox < WOUT) {
                        float2 v0 = make_float2(c[mt][q][0], c[mt][q][1]);
                        float2 v1 = make_float2(c[mt][q][2], c[mt][q][3]);
                        *reinterpret_cast<float2*>(out + base0 + ox)          = v0;
                        *reinterpret_cast<float2*>(out + base0 + coStep + ox) = v1;
                    }
                }
            }
        }

        // ---- drain prefetch, convert into ring, flip
        if (i + 1 < NTILES) {
            CP_WAIT0();
            __syncthreads();
            convert_rows(smem, sb, yin0 + 6, 4, t);
        }
        __syncthreads();
    }
}

extern "C" void kernel_launch(void* const* d_in, const int* in_sizes, int n_in,
                              void* d_out, int out_size)
{
    const float* x    = (const float*)d_in[0];
    const float* w    = (const float*)d_in[1];
    const float* bias = (const float*)d_in[2];
    float*       out  = (float*)d_out;

    pack_w_kernel<<<36, 256>>>(w);

    cudaFuncSetAttribute(conv_mma_kernel,
                         cudaFuncAttributeMaxDynamicSharedMemorySize, SMEM_TOTAL);

    dim3 grid(8, 16, NB);               // 8 x-tiles, 16 y-walks, 16 batches
    conv_mma_kernel<<<grid, THREADS, SMEM_TOTAL>>>(x, bias, out);
}

// round 16
// speedup vs baseline: 1.0782x; 1.0782x over previous
#include <cuda_runtime.h>
#include <cuda_fp16.h>
#include <cstdint>

// ---------------- problem dims ----------------
#define CIN   32
#define COUT  32
#define HIN   512
#define WIN   512
#define HOUT  510
#define WOUT  510
#define NB    16

// ---------------- tiling ----------------
#define TY      4              // output rows per tile
#define TPX     64             // output px per CTA
#define XPX     68             // staged px (64 + 2 halo + pad)
#define THREADS 256
#define NTILES  8              // y-tiles walked per CTA

// ---------------- smem ----------------
#define ROWB       80
#define XSLOT      (XPX * ROWB)         // 5440
#define RSLOTS     10
#define RING_BYTES (RSLOTS * XSLOT)     // 54400
#define FROW       272
#define FSLOT      (32 * FROW)          // 8704
#define F_OFF      RING_BYTES           // 54400
#define F_BYTES    (4 * FSLOT)          // 34816
#define W_OFF      (F_OFF + F_BYTES)    // 89216
#define W_BYTES    (288 * ROWB)         // 23040
#define SMEM_TOTAL (W_OFF + W_BYTES)    // 112256 (2 CTAs/SM)

__device__ __align__(16) __half w_packed[288 * 40];

__device__ __forceinline__ uint32_t smem_u32(const void* p) {
    uint32_t a;
    asm("{ .reg .u64 t; cvta.to.shared.u64 t, %1; cvt.u32.u64 %0, t; }"
        : "=r"(a) : "l"(p));
    return a;
}
__device__ __forceinline__ uint32_t h2u(__half2 h) {
    return *reinterpret_cast<uint32_t*>(&h);
}

#define STS128(addr, a, b, c, d) \
    asm volatile("st.shared.v4.b32 [%0], {%1,%2,%3,%4};" \
        :: "r"(addr), "r"(a), "r"(b), "r"(c), "r"(d) : "memory")

#define LDSM4(r, addr) \
    asm volatile("ldmatrix.sync.aligned.m8n8.x4.shared.b16 {%0,%1,%2,%3}, [%4];" \
        : "=r"((r)[0]), "=r"((r)[1]), "=r"((r)[2]), "=r"((r)[3]) : "r"(addr))

#define MMA_F16(c, a, b0, b1) \
    asm volatile("mma.sync.aligned.m16n8k16.row.col.f32.f16.f16.f32 " \
        "{%0,%1,%2,%3}, {%4,%5,%6,%7}, {%8,%9}, {%0,%1,%2,%3};" \
        : "+f"((c)[0]), "+f"((c)[1]), "+f"((c)[2]), "+f"((c)[3]) \
        : "r"((a)[0]), "r"((a)[1]), "r"((a)[2]), "r"((a)[3]), "r"(b0), "r"(b1))

#define CP_ASYNC16(smem, gmem) \
    asm volatile("cp.async.cg.shared.global [%0], [%1], 16;" \
        :: "r"(smem), "l"(gmem) : "memory")
#define CP_COMMIT()  asm volatile("cp.async.commit_group;" ::: "memory")
#define CP_WAIT0()   asm volatile("cp.async.wait_group 0;" ::: "memory")

// =====================================================================
// setup: w (OIHW fp32) -> w_packed [kk*32+co][ci] fp16 (40-half rows)
// =====================================================================
__global__ void pack_w_kernel(const float* __restrict__ w)
{
    int i = blockIdx.x * 256 + threadIdx.x;
    if (i < 288 * 32) {
        int row = i >> 5;
        int ci  = i & 31;
        int kk  = row >> 5;
        int co  = row & 31;
        w_packed[row * 40 + ci] = __float2half_rn(w[(co * 32 + ci) * 9 + kk]);
    }
}

// =====================================================================
// staging helpers
// =====================================================================
__device__ __forceinline__ void issue_rows(const float* __restrict__ x,
                                           uint32_t sb, int nb, int x0,
                                           int base_row, int nrows, int t)
{
    const int nchunks = nrows * 32 * 17;
    #pragma unroll 1
    for (int chunk = t; chunk < nchunks; chunk += THREADS) {
        const int k   = chunk % 17;
        const int rem = chunk / 17;
        const int ci  = rem & 31;
        const int j   = rem >> 5;
        const int y_in = base_row + j;
        const int gx0  = x0 + k * 4;
        if (y_in < HIN && gx0 + 3 < WIN) {
            const float* g =
                x + ((size_t)(nb * CIN + ci) * HIN + y_in) * WIN + gx0;
            CP_ASYNC16(sb + F_OFF + (uint32_t)((j * 32 + ci) * FROW + k * 16), g);
        }
    }
}

__device__ __forceinline__ void convert_rows(const char* smem, uint32_t sb,
                                             int base_row, int nrows, int t)
{
    const float* fs = reinterpret_cast<const float*>(smem + F_OFF);
    const int items = nrows * 4 * XPX;
    #pragma unroll 1
    for (int it = t; it < items; it += THREADS) {
        const int px  = it % XPX;
        const int rem = it / XPX;
        const int o   = rem & 3;
        const int j   = rem >> 2;
        const int slot = (base_row + j) % RSLOTS;
        const float* src = fs + (j * 32 + o * 8) * XPX + px;
        float v[8];
        #pragma unroll
        for (int q = 0; q < 8; ++q) v[q] = src[q * XPX];
        __half2 h0 = __floats2half2_rn(v[0], v[1]);
        __half2 h1 = __floats2half2_rn(v[2], v[3]);
        __half2 h2 = __floats2half2_rn(v[4], v[5]);
        __half2 h3 = __floats2half2_rn(v[6], v[7]);
        STS128(sb + (uint32_t)slot * XSLOT + (uint32_t)px * ROWB + (uint32_t)o * 16,
               h2u(h0), h2u(h1), h2u(h2), h2u(h3));
    }
}

// =====================================================================
// main kernel: 8 warps m32n32, ring-buffered persistent, pipelined frags
// =====================================================================
__global__ __launch_bounds__(THREADS, 2)
void conv_mma_kernel(const float* __restrict__ x,
                     const float* __restrict__ bias,
                     float* __restrict__ out)
{
    extern __shared__ char smem[];
    const uint32_t sb = smem_u32(smem);
    const int t    = threadIdx.x;
    const int wid  = t >> 5;
    const int lane = t & 31;

    const int xt  = blockIdx.x;           // 0..7
    const int gy  = blockIdx.y;           // 0..15
    const int nb  = blockIdx.z;           // 0..15
    const int x0  = xt * TPX;
    const int yt0 = gy * NTILES;
    const int row0 = yt0 * TY;

    // ---- stage W once per CTA
    {
        const uint4* src = reinterpret_cast<const uint4*>(w_packed);
        #pragma unroll 1
        for (int i = t; i < W_BYTES / 16; i += THREADS) {
            uint4 v = src[i];
            STS128(sb + W_OFF + (uint32_t)i * 16, v.x, v.y, v.z, v.w);
        }
    }

    // ---- prologue: rows row0..row0+3, then row0+4..row0+5
    issue_rows(x, sb, nb, x0, row0, 4, t);
    CP_COMMIT(); CP_WAIT0(); __syncthreads();
    convert_rows(smem, sb, row0, 4, t);
    __syncthreads();
    issue_rows(x, sb, nb, x0, row0 + 4, 2, t);
    CP_COMMIT(); CP_WAIT0(); __syncthreads();
    convert_rows(smem, sb, row0 + 4, 2, t);
    __syncthreads();

    // lane constants
    const int a_row   = lane & 15;
    const int a_chunk = lane >> 4;
    const int b_n     = (lane & 7) | ((lane >> 4) << 3);
    const int b_chunk = (lane >> 3) & 1;
    const int g  = lane >> 2;
    const int tg = lane & 3;

    const int r   = wid >> 1;          // output row 0..3
    const int pxw = (wid & 1) * 32;    // px chunk base

    const uint32_t aRowBase = sb + W_OFF + (uint32_t)a_row * ROWB;

    float bv[2][2];
    #pragma unroll
    for (int mt = 0; mt < 2; ++mt) {
        bv[mt][0] = __ldg(bias + mt * 16 + g);
        bv[mt][1] = __ldg(bias + mt * 16 + 8 + g);
    }

    #pragma unroll 1
    for (int i = 0; i < NTILES; ++i) {
        const int yin0 = (yt0 + i) * TY;

        // ---- prefetch the 4 new rows for tile i+1
        if (i + 1 < NTILES) {
            issue_rows(x, sb, nb, x0, yin0 + 6, 4, t);
            CP_COMMIT();
        }

        // ---- ring slot bases for the 3 ky rows this warp touches
        uint32_t XsB[3];
        #pragma unroll
        for (int ky = 0; ky < 3; ++ky)
            XsB[ky] = sb + (uint32_t)((yin0 + r + ky) % RSLOTS) * XSLOT;

        // ---- accumulators
        float c[2][4][4];
        #pragma unroll
        for (int mt = 0; mt < 2; ++mt)
            #pragma unroll
            for (int q = 0; q < 4; ++q) {
                c[mt][q][0] = bv[mt][0]; c[mt][q][1] = bv[mt][0];
                c[mt][q][2] = bv[mt][1]; c[mt][q][3] = bv[mt][1];
            }

        // ---- software-pipelined 18-step mainloop (ky,kx,kc flattened)
        uint32_t af[2][2][4], bf[2][2][4];

        // load step 0
        {
            const uint32_t aAddr = aRowBase;            // kk=0, kc=0
            LDSM4(af[0][0], aAddr + (uint32_t)a_chunk * 16);
            LDSM4(af[0][1], aAddr + 16 * ROWB + (uint32_t)a_chunk * 16);
            const uint32_t bOff = (uint32_t)b_chunk * 16;
            #pragma unroll
            for (int g2 = 0; g2 < 2; ++g2) {
                const int prow = pxw + 0 + g2 * 16 + b_n;
                LDSM4(bf[0][g2], XsB[0] + (uint32_t)prow * ROWB + bOff);
            }
        }

        #pragma unroll
        for (int s = 0; s < 18; ++s) {
            const int cur = s & 1;
            if (s + 1 < 18) {
                const int sn  = s + 1;
                const int nky = sn / 6;
                const int nkx = (sn >> 1) % 3;
                const int nkc = sn & 1;
                const int nkk = nky * 3 + nkx;
                const uint32_t aAddr =
                    aRowBase + (uint32_t)(nkk * 32) * ROWB
                             + (uint32_t)(2 * nkc + a_chunk) * 16;
                LDSM4(af[cur ^ 1][0], aAddr);
                LDSM4(af[cur ^ 1][1], aAddr + 16 * ROWB);
                const uint32_t bOff = (uint32_t)(2 * nkc + b_chunk) * 16;
                #pragma unroll
                for (int g2 = 0; g2 < 2; ++g2) {
                    const int prow = pxw + nkx + g2 * 16 + b_n;
                    LDSM4(bf[cur ^ 1][g2],
                          XsB[nky] + (uint32_t)prow * ROWB + bOff);
                }
            }
            #pragma unroll
            for (int mt = 0; mt < 2; ++mt)
                #pragma unroll
                for (int q = 0; q < 4; ++q) {
                    const int g2 = q >> 1;
                    const int e  = (q & 1) * 2;
                    MMA_F16(c[mt][q], af[cur][mt], bf[cur][g2][e], bf[cur][g2][e + 1]);
                }
        }

        // ---- store
        const int oy = yin0 + r;
        if (oy < HOUT) {
            #pragma unroll
            for (int mt = 0; mt < 2; ++mt) {
                const size_t base0 =
                    ((size_t)(nb * COUT + mt * 16 + g) * HOUT + oy) * (size_t)WOUT;
                const size_t coStep = (size_t)8 * HOUT * WOUT;
                #pragma unroll
                for (int q = 0; q < 4; ++q) {
                    const int ox = x0 + pxw + q * 8 + 2 * tg;
                    if (ox < WOUT) {
                        float2 v0 = make_float2(c[mt][q][0], c[mt][q][1]);
                        float2 v1 = make_float2(c[mt][q][2], c[mt][q][3]);
                        *reinterpret_cast<float2*>(out + base0 + ox)          = v0;
                        *reinterpret_cast<float2*>(out + base0 + coStep + ox) = v1;
                    }
                }
            }
        }

        // ---- drain prefetch, convert into ring, flip
        if (i + 1 < NTILES) {
            CP_WAIT0();
            __syncthreads();
            convert_rows(smem, sb, yin0 + 6, 4, t);
        }
        __syncthreads();
    }
}

extern "C" void kernel_launch(void* const* d_in, const int* in_sizes, int n_in,
                              void* d_out, int out_size)
{
    const float* x    = (const float*)d_in[0];
    const float* w    = (const float*)d_in[1];
    const float* bias = (const float*)d_in[2];
    float*       out  = (float*)d_out;

    pack_w_kernel<<<36, 256>>>(w);

    cudaFuncSetAttribute(conv_mma_kernel,
                         cudaFuncAttributeMaxDynamicSharedMemorySize, SMEM_TOTAL);

    dim3 grid(8, 16, NB);               // 8 x-tiles, 16 y-walks, 16 batches
    conv_mma_kernel<<<grid, THREADS, SMEM_TOTAL>>>(x, bias, out);
}